// round 14
// baseline (speedup 1.0000x reference)
#include <cuda_runtime.h>
#include <cuda_bf16.h>
#include <math.h>

#define SEQ 2048
#define BATCH 2
#define DIN 768
#define NHEAD 8
#define HDIM 64
#define NPROJ 1024          // 512 start + 512 end, fused
#define NEGV 1000000000000.0f

// Scratch
__device__ __nv_bfloat16 g_SR[BATCH * NHEAD * SEQ * HDIM];
__device__ __nv_bfloat16 g_ER[BATCH * NHEAD * SEQ * HDIM];
__device__ __nv_bfloat16 g_Xb[BATCH * SEQ * DIN];        // X in bf16
__device__ __nv_bfloat16 g_Wt[NPROJ * DIN];              // W^T (n-major, k-contiguous)
__device__ float2        g_tab[SEQ * 32];                // (sin, cos) per (pos, freq)

// ---------------------------------------------------------------------------
// Merged prep kernel: blocks [0,768) convert X (4 float4/thread),
// [768,1536) transpose W, [1536,1792) rope table.
// ---------------------------------------------------------------------------
__global__ __launch_bounds__(256) void prep_kernel(
    const float* __restrict__ X,
    const float* __restrict__ Ws, const float* __restrict__ We)
{
    const int bid = blockIdx.x;
    const int tid = threadIdx.x;

    if (bid < 768) {
        const int base = bid * 1024 + tid;
        float4 v[4];
#pragma unroll
        for (int j = 0; j < 4; j++) v[j] = ((const float4*)X)[base + j * 256];
#pragma unroll
        for (int j = 0; j < 4; j++) {
            __nv_bfloat162 p0, p1;
            p0.x = __float2bfloat16(v[j].x); p0.y = __float2bfloat16(v[j].y);
            p1.x = __float2bfloat16(v[j].z); p1.y = __float2bfloat16(v[j].w);
            uint2 st; st.x = *(unsigned*)&p0; st.y = *(unsigned*)&p1;
            ((uint2*)g_Xb)[base + j * 256] = st;
        }
    } else if (bid < 1536) {
        __shared__ float t[32][33];
        const int id = bid - 768;
        const int k0 = (id % 24) * 32;
        const int n0 = (id / 24) * 32;
        const int tx = tid & 31, ty = tid >> 5;
        const int nn = n0 + tx;
        const float* __restrict__ src = (nn < 512) ? Ws : We;
        const int ncol = nn & 511;
#pragma unroll
        for (int j = 0; j < 32; j += 8)
            t[ty + j][tx] = src[(size_t)(k0 + ty + j) * 512 + ncol];
        __syncthreads();
#pragma unroll
        for (int j = 0; j < 32; j += 8) {
            const int n = n0 + ty + j;
            g_Wt[(size_t)n * DIN + k0 + tx] = __float2bfloat16(t[tx][ty + j]);
        }
    } else {
        const int idx = (bid - 1536) * 256 + tid;
        const int spos = idx >> 5;
        const int i = idx & 31;
        const float inv = (float)exp(-(double)i * 9.210340371976184 / 32.0);
        float s, c;
        sincosf((float)spos * inv, &s, &c);
        g_tab[idx] = make_float2(s, c);
    }
}

// ---------------------------------------------------------------------------
// Shared HMMA helpers
// ---------------------------------------------------------------------------
__device__ __forceinline__ unsigned smem_u32(const void* p) {
    return (unsigned)__cvta_generic_to_shared(p);
}
__device__ __forceinline__ void ldm_x4(unsigned addr, unsigned& r0, unsigned& r1,
                                       unsigned& r2, unsigned& r3) {
    asm volatile("ldmatrix.sync.aligned.m8n8.x4.shared.b16 {%0,%1,%2,%3}, [%4];"
                 : "=r"(r0), "=r"(r1), "=r"(r2), "=r"(r3) : "r"(addr));
}
__device__ __forceinline__ void mma_bf16(float c[4], unsigned a0, unsigned a1,
                                         unsigned a2, unsigned a3,
                                         unsigned b0, unsigned b1) {
    asm volatile("mma.sync.aligned.m16n8k16.row.col.f32.bf16.bf16.f32 "
                 "{%0,%1,%2,%3}, {%4,%5,%6,%7}, {%8,%9}, {%0,%1,%2,%3};"
                 : "+f"(c[0]), "+f"(c[1]), "+f"(c[2]), "+f"(c[3])
                 : "r"(a0), "r"(a1), "r"(a2), "r"(a3), "r"(b0), "r"(b1));
}
__device__ __forceinline__ void cp_async16(unsigned saddr, const void* gptr) {
    asm volatile("cp.async.cg.shared.global [%0], [%1], 16;" :: "r"(saddr), "l"(gptr));
}
#define CP_COMMIT() asm volatile("cp.async.commit_group;")
#define CP_WAIT(n)  asm volatile("cp.async.wait_group %0;" :: "n"(n))
#define SWZ(off) ((off) ^ (((off) >> 3) & 0x70))

// ---------------------------------------------------------------------------
// Projection GEMM with INTERLEAVED masked-region fill.
// 256 CTAs (one wave). Each CTA, besides its 128x128 GEMM tile, writes up to
// 8 below-diagonal output tiles (value = -(1-pad)*NEG - NEG), one per K-step
// ks=0..7, as fire-and-forget stores that overlap the tensor-core mainloop.
// ---------------------------------------------------------------------------
#define KSTEPS (DIN / 64)    // 12

__global__ __launch_bounds__(256) void proj_mma_kernel(
    const float* __restrict__ bs, const float* __restrict__ be,
    const float* __restrict__ mask, float* __restrict__ out)
{
    extern __shared__ __align__(1024) char smem[];
    char* bufA[3] = { smem,         smem + 32768, smem + 65536 };
    char* bufB[3] = { smem + 16384, smem + 49152, smem + 81920 };

    const int n0 = blockIdx.x * 128;
    const int m0 = blockIdx.y * 128;
    const int tid = threadIdx.x;
    const int fid = blockIdx.y * 8 + blockIdx.x;   // 0..255: fill-work id

    // fill lane geometry
    const int cb4f = (tid & 31) * 4;
    const int r0f  = tid >> 5;

    const int lrow[4] = { (tid + 0) >> 3, (tid + 256) >> 3, (tid + 512) >> 3, (tid + 768) >> 3 };
    const int lcb = (tid & 7) * 16;
    unsigned lsw[4];
#pragma unroll
    for (int i = 0; i < 4; i++) lsw[i] = SWZ((unsigned)(lrow[i] * 128 + lcb));

    const char* Agbase = (const char*)g_Xb + (size_t)m0 * (DIN * 2) + lcb;
    const char* Bgbase = (const char*)g_Wt + (size_t)n0 * (DIN * 2) + lcb;

#pragma unroll
    for (int s = 0; s < 2; s++) {
        const size_t koff = (size_t)s * 128;
#pragma unroll
        for (int i = 0; i < 4; i++) {
            cp_async16(smem_u32(bufA[s]) + lsw[i], Agbase + (size_t)lrow[i] * (DIN * 2) + koff);
            cp_async16(smem_u32(bufB[s]) + lsw[i], Bgbase + (size_t)lrow[i] * (DIN * 2) + koff);
        }
        CP_COMMIT();
    }

    const int wid = tid >> 5;
    const int lane = tid & 31;
    const int wm = (wid & 1) * 64;
    const int wn = (wid >> 1) * 32;

    const int aRowL = (lane & 7) + ((lane >> 3) & 1) * 8;
    const int aColB = (lane >> 4) * 16;
    const int bRowL = (lane & 7) + (lane >> 4) * 8;
    const int bColB = ((lane >> 3) & 1) * 16;

    float acc[4][4][4];
#pragma unroll
    for (int mf = 0; mf < 4; mf++)
#pragma unroll
        for (int nf = 0; nf < 4; nf++)
#pragma unroll
            for (int r = 0; r < 4; r++) acc[mf][nf][r] = 0.0f;

    int stage = 0;
    int pstage = 2;
    for (int ks = 0; ks < KSTEPS; ks++) {
        if (ks + 2 < KSTEPS) { CP_WAIT(1); } else { CP_WAIT(0); }
        __syncthreads();

        if (ks + 2 < KSTEPS) {
            const size_t koff = (size_t)(ks + 2) * 128;
#pragma unroll
            for (int i = 0; i < 4; i++) {
                cp_async16(smem_u32(bufA[pstage]) + lsw[i], Agbase + (size_t)lrow[i] * (DIN * 2) + koff);
                cp_async16(smem_u32(bufB[pstage]) + lsw[i], Bgbase + (size_t)lrow[i] * (DIN * 2) + koff);
            }
            CP_COMMIT();
        }

        // ---- interleaved fill: one below-diagonal 128x128 tile per K-step ----
        if (ks < 8) {
            const int r = fid * 8 + ks;
            if (r < 1920) {
                const int z = r / 120;           // b*8+o
                const int t = r % 120;           // below-diag tile id within z
                int my = (int)((1.0f + sqrtf(8.0f * (float)t + 1.0f)) * 0.5f);
                if (my * (my - 1) / 2 > t) my--;
                if ((my + 1) * my / 2 <= t) my++;
                const int nx = t - my * (my - 1) / 2;
                const float4 pv = *(const float4*)&mask[(z >> 3) * SEQ + nx * 128 + cb4f];
                float4 v;
                v.x = -(1.0f - pv.x) * NEGV - NEGV;
                v.y = -(1.0f - pv.y) * NEGV - NEGV;
                v.z = -(1.0f - pv.z) * NEGV - NEGV;
                v.w = -(1.0f - pv.w) * NEGV - NEGV;
                float* base = out + ((size_t)z * SEQ + my * 128) * SEQ + nx * 128 + cb4f;
#pragma unroll
                for (int i = 0; i < 16; i++)
                    *(float4*)(base + (size_t)(r0f + i * 8) * SEQ) = v;
            }
        }

        const unsigned sAb = smem_u32(bufA[stage]);
        const unsigned sBb = smem_u32(bufB[stage]);
#pragma unroll
        for (int k = 0; k < 4; k++) {
            const int kb = k * 32;
            unsigned a[4][4];
#pragma unroll
            for (int mf = 0; mf < 4; mf++) {
                const unsigned off = (unsigned)((wm + mf * 16 + aRowL) * 128 + kb + aColB);
                ldm_x4(sAb + SWZ(off), a[mf][0], a[mf][1], a[mf][2], a[mf][3]);
            }
            unsigned bb[8];
#pragma unroll
            for (int np = 0; np < 2; np++) {
                const unsigned off = (unsigned)((wn + np * 16 + bRowL) * 128 + kb + bColB);
                ldm_x4(sBb + SWZ(off), bb[np * 4 + 0], bb[np * 4 + 1],
                       bb[np * 4 + 2], bb[np * 4 + 3]);
            }
#pragma unroll
            for (int mf = 0; mf < 4; mf++)
#pragma unroll
                for (int nf = 0; nf < 4; nf++) {
                    const int np = nf >> 1, sub = nf & 1;
                    mma_bf16(acc[mf][nf], a[mf][0], a[mf][1], a[mf][2], a[mf][3],
                             bb[np * 4 + sub * 2], bb[np * 4 + sub * 2 + 1]);
                }
        }

        stage = (stage == 2) ? 0 : stage + 1;
        pstage = (pstage == 2) ? 0 : pstage + 1;
    }

    // Epilogue: bias + rope + bf16 store.
    const int q = lane >> 2;
    const int nlo = (lane & 3) * 2;

#pragma unroll
    for (int nf = 0; nf < 4; nf++) {
        const int n = n0 + wn + nf * 8 + nlo;
        const int which = n >> 9;
        const int nc = n & 511;
        const int o = nc >> 6;
        const int h = n & 63;
        const int f0 = h & 31;
        const float* bp = which ? be : bs;
        const float b0 = bp[nc], b1 = bp[nc + 1];
        const float scale = which ? 1.0f : 0.125f;
        __nv_bfloat16* dstb = which ? g_ER : g_SR;
#pragma unroll
        for (int mf = 0; mf < 4; mf++)
#pragma unroll
            for (int half = 0; half < 2; half++) {
                const int m = m0 + wm + mf * 16 + q + half * 8;
                const int bidx = m >> 11;
                const int spos = m & 2047;
                const float4 sc = *(const float4*)&g_tab[spos * 32 + f0];
                const float v0 = acc[mf][nf][half * 2 + 0] + b0;
                const float v1 = acc[mf][nf][half * 2 + 1] + b1;
                const float r0 = (v0 * sc.y - v1 * sc.x) * scale;
                const float r1 = (v1 * sc.w + v0 * sc.z) * scale;
                __nv_bfloat162 p;
                p.x = __float2bfloat16(r0);
                p.y = __float2bfloat16(r1);
                *(unsigned*)&dstb[(((size_t)(bidx * NHEAD + o)) * SEQ + spos) * HDIM + h]
                    = *(unsigned*)&p;
            }
    }
}

// ---------------------------------------------------------------------------
// Kernel 2: logits; below-diagonal tiles already written by proj's fill.
// ---------------------------------------------------------------------------
__global__ __launch_bounds__(256) void logits_kernel(
    const float* __restrict__ mask, float* __restrict__ out)
{
    const int z = blockIdx.z;
    const int b = z >> 3;
    const int m0 = blockIdx.y * 128;
    const int n0 = blockIdx.x * 128;
    const int tid = threadIdx.x;

    if (n0 + 127 < m0) return;   // written by proj fill

    const char* __restrict__ Ag = (const char*)(g_SR + (size_t)z * SEQ * HDIM);
    const char* __restrict__ Bg = (const char*)(g_ER + (size_t)z * SEQ * HDIM);

    __shared__ __align__(1024) char sA[128 * 128];
    __shared__ __align__(1024) char sB[128 * 128];

#pragma unroll
    for (int i = 0; i < 4; i++) {
        const int c = tid + i * 256;
        const int row = c >> 3;
        const int cb = (c & 7) * 16;
        const unsigned sw = SWZ((unsigned)(row * 128 + cb));
        *(uint4*)(sA + sw) = *(const uint4*)(Ag + (size_t)(m0 + row) * 128 + cb);
        *(uint4*)(sB + sw) = *(const uint4*)(Bg + (size_t)(n0 + row) * 128 + cb);
    }
    __syncthreads();

    const int wid = tid >> 5;
    const int lane = tid & 31;
    const int wm = (wid & 1) * 64;
    const int wn = (wid >> 1) * 32;

    const unsigned sAb = smem_u32(sA);
    const unsigned sBb = smem_u32(sB);

    float acc[4][4][4];
#pragma unroll
    for (int mf = 0; mf < 4; mf++)
#pragma unroll
        for (int nf = 0; nf < 4; nf++)
#pragma unroll
            for (int r = 0; r < 4; r++) acc[mf][nf][r] = 0.0f;

    const int aRowL = (lane & 7) + ((lane >> 3) & 1) * 8;
    const int aColB = (lane >> 4) * 16;
    const int bRowL = (lane & 7) + (lane >> 4) * 8;
    const int bColB = ((lane >> 3) & 1) * 16;

#pragma unroll
    for (int k = 0; k < 4; k++) {
        const int kb = k * 32;
        unsigned a[4][4];
#pragma unroll
        for (int mf = 0; mf < 4; mf++) {
            const unsigned off = (unsigned)((wm + mf * 16 + aRowL) * 128 + kb + aColB);
            ldm_x4(sAb + SWZ(off), a[mf][0], a[mf][1], a[mf][2], a[mf][3]);
        }
        unsigned bb[8];
#pragma unroll
        for (int np = 0; np < 2; np++) {
            const unsigned off = (unsigned)((wn + np * 16 + bRowL) * 128 + kb + bColB);
            ldm_x4(sBb + SWZ(off), bb[np * 4 + 0], bb[np * 4 + 1],
                   bb[np * 4 + 2], bb[np * 4 + 3]);
        }
#pragma unroll
        for (int mf = 0; mf < 4; mf++) {
#pragma unroll
            for (int nf = 0; nf < 4; nf++) {
                const int np = nf >> 1;
                const int sub = nf & 1;
                mma_bf16(acc[mf][nf], a[mf][0], a[mf][1], a[mf][2], a[mf][3],
                         bb[np * 4 + sub * 2], bb[np * 4 + sub * 2 + 1]);
            }
        }
    }

    const int q = lane >> 2;
    const int nlo = (lane & 3) * 2;

    float2 pv[4];
#pragma unroll
    for (int nf = 0; nf < 4; nf++) {
        const int n = n0 + wn + nf * 8 + nlo;
        pv[nf] = *(const float2*)&mask[b * SEQ + n];
    }

#pragma unroll
    for (int mf = 0; mf < 4; mf++) {
#pragma unroll
        for (int half = 0; half < 2; half++) {
            const int m = m0 + wm + mf * 16 + q + half * 8;
            float* rowp = out + ((size_t)z * SEQ + m) * SEQ;
#pragma unroll
            for (int nf = 0; nf < 4; nf++) {
                const int n = n0 + wn + nf * 8 + nlo;
                float x0 = acc[mf][nf][half * 2 + 0];
                float x1 = acc[mf][nf][half * 2 + 1];
                const float p0 = pv[nf].x, p1 = pv[nf].y;
                x0 = x0 * p0 - (1.0f - p0) * NEGV;
                x1 = x1 * p1 - (1.0f - p1) * NEGV;
                if (n < m)     x0 -= NEGV;
                if (n + 1 < m) x1 -= NEGV;
                *(float2*)(rowp + n) = make_float2(x0, x1);
            }
        }
    }
}

extern "C" void kernel_launch(void* const* d_in, const int* in_sizes, int n_in,
                              void* d_out, int out_size)
{
    const float* X    = (const float*)d_in[0];
    const float* mask = (const float*)d_in[1];
    const float* Ws   = (const float*)d_in[2];
    const float* bs   = (const float*)d_in[3];
    const float* We   = (const float*)d_in[4];
    const float* be   = (const float*)d_in[5];
    float* out = (float*)d_out;

    cudaFuncSetAttribute(proj_mma_kernel,
                         cudaFuncAttributeMaxDynamicSharedMemorySize, 98304);

    prep_kernel<<<1792, 256>>>(X, Ws, We);

    dim3 g1(NPROJ / 128, BATCH * SEQ / 128);             // (8, 32): GEMM + inline fill
    proj_mma_kernel<<<g1, 256, 98304>>>(bs, be, mask, out);

    dim3 g2(SEQ / 128, SEQ / 128, BATCH * NHEAD);        // (16, 16, 16)
    logits_kernel<<<g2, 256>>>(mask, out);
}

// round 15
// speedup vs baseline: 1.0812x; 1.0812x over previous
#include <cuda_runtime.h>
#include <cuda_bf16.h>
#include <math.h>

#define SEQ 2048
#define BATCH 2
#define DIN 768
#define NHEAD 8
#define HDIM 64
#define NPROJ 1024          // 512 start + 512 end, fused
#define NEGV 1000000000000.0f

// Scratch
__device__ __nv_bfloat16 g_SR[BATCH * NHEAD * SEQ * HDIM];
__device__ __nv_bfloat16 g_ER[BATCH * NHEAD * SEQ * HDIM];
__device__ __nv_bfloat16 g_Xb[BATCH * SEQ * DIN];        // X in bf16
__device__ __nv_bfloat16 g_Wt[NPROJ * DIN];              // W^T (n-major, k-contiguous)
__device__ float2        g_tab[SEQ * 32];                // (sin, cos) per (pos, freq)

// ---------------------------------------------------------------------------
// Merged prep kernel: blocks [0,768) convert X (4 float4/thread),
// [768,1536) transpose W, [1536,1792) rope table (fp32 exp2f, no FP64).
// ---------------------------------------------------------------------------
__global__ __launch_bounds__(256) void prep_kernel(
    const float* __restrict__ X,
    const float* __restrict__ Ws, const float* __restrict__ We)
{
    const int bid = blockIdx.x;
    const int tid = threadIdx.x;

    if (bid < 768) {
        const int base = bid * 1024 + tid;
        float4 v[4];
#pragma unroll
        for (int j = 0; j < 4; j++) v[j] = ((const float4*)X)[base + j * 256];
#pragma unroll
        for (int j = 0; j < 4; j++) {
            __nv_bfloat162 p0, p1;
            p0.x = __float2bfloat16(v[j].x); p0.y = __float2bfloat16(v[j].y);
            p1.x = __float2bfloat16(v[j].z); p1.y = __float2bfloat16(v[j].w);
            uint2 st; st.x = *(unsigned*)&p0; st.y = *(unsigned*)&p1;
            ((uint2*)g_Xb)[base + j * 256] = st;
        }
    } else if (bid < 1536) {
        __shared__ float t[32][33];
        const int id = bid - 768;
        const int k0 = (id % 24) * 32;
        const int n0 = (id / 24) * 32;
        const int tx = tid & 31, ty = tid >> 5;
        const int nn = n0 + tx;
        const float* __restrict__ src = (nn < 512) ? Ws : We;
        const int ncol = nn & 511;
#pragma unroll
        for (int j = 0; j < 32; j += 8)
            t[ty + j][tx] = src[(size_t)(k0 + ty + j) * 512 + ncol];
        __syncthreads();
#pragma unroll
        for (int j = 0; j < 32; j += 8) {
            const int n = n0 + ty + j;
            g_Wt[(size_t)n * DIN + k0 + tx] = __float2bfloat16(t[tx][ty + j]);
        }
    } else {
        // rope table, 65536 entries: inv = 10000^(-i/32) = exp2f(-i*log2(1e4)/32)
        const int idx = (bid - 1536) * 256 + tid;
        const int spos = idx >> 5;
        const int i = idx & 31;
        const float inv = exp2f(-(float)i * 0.41524101186092029f);
        float s, c;
        sincosf((float)spos * inv, &s, &c);
        g_tab[idx] = make_float2(s, c);
    }
}

// ---------------------------------------------------------------------------
// Shared HMMA helpers
// ---------------------------------------------------------------------------
__device__ __forceinline__ unsigned smem_u32(const void* p) {
    return (unsigned)__cvta_generic_to_shared(p);
}
__device__ __forceinline__ void ldm_x4(unsigned addr, unsigned& r0, unsigned& r1,
                                       unsigned& r2, unsigned& r3) {
    asm volatile("ldmatrix.sync.aligned.m8n8.x4.shared.b16 {%0,%1,%2,%3}, [%4];"
                 : "=r"(r0), "=r"(r1), "=r"(r2), "=r"(r3) : "r"(addr));
}
__device__ __forceinline__ void mma_bf16(float c[4], unsigned a0, unsigned a1,
                                         unsigned a2, unsigned a3,
                                         unsigned b0, unsigned b1) {
    asm volatile("mma.sync.aligned.m16n8k16.row.col.f32.bf16.bf16.f32 "
                 "{%0,%1,%2,%3}, {%4,%5,%6,%7}, {%8,%9}, {%0,%1,%2,%3};"
                 : "+f"(c[0]), "+f"(c[1]), "+f"(c[2]), "+f"(c[3])
                 : "r"(a0), "r"(a1), "r"(a2), "r"(a3), "r"(b0), "r"(b1));
}
__device__ __forceinline__ void cp_async16(unsigned saddr, const void* gptr) {
    asm volatile("cp.async.cg.shared.global [%0], [%1], 16;" :: "r"(saddr), "l"(gptr));
}
#define CP_COMMIT() asm volatile("cp.async.commit_group;")
#define CP_WAIT(n)  asm volatile("cp.async.wait_group %0;" :: "n"(n))
#define SWZ(off) ((off) ^ (((off) >> 3) & 0x70))

// ---------------------------------------------------------------------------
// Projection GEMM: C[4096][1024] = Xb @ Wt^T, bf16 HMMA, fused bias+rope.
// CTA 128x128, BK=64, 3-stage cp.async pipeline, ONE barrier per K-step.
// ---------------------------------------------------------------------------
#define KSTEPS (DIN / 64)    // 12

__global__ __launch_bounds__(256) void proj_mma_kernel(
    const float* __restrict__ bs, const float* __restrict__ be)
{
    extern __shared__ __align__(1024) char smem[];
    char* bufA[3] = { smem,         smem + 32768, smem + 65536 };
    char* bufB[3] = { smem + 16384, smem + 49152, smem + 81920 };

    const int n0 = blockIdx.x * 128;
    const int m0 = blockIdx.y * 128;
    const int tid = threadIdx.x;

    const int lrow[4] = { (tid + 0) >> 3, (tid + 256) >> 3, (tid + 512) >> 3, (tid + 768) >> 3 };
    const int lcb = (tid & 7) * 16;
    unsigned lsw[4];
#pragma unroll
    for (int i = 0; i < 4; i++) lsw[i] = SWZ((unsigned)(lrow[i] * 128 + lcb));

    const char* Agbase = (const char*)g_Xb + (size_t)m0 * (DIN * 2) + lcb;
    const char* Bgbase = (const char*)g_Wt + (size_t)n0 * (DIN * 2) + lcb;

#pragma unroll
    for (int s = 0; s < 2; s++) {
        const size_t koff = (size_t)s * 128;
#pragma unroll
        for (int i = 0; i < 4; i++) {
            cp_async16(smem_u32(bufA[s]) + lsw[i], Agbase + (size_t)lrow[i] * (DIN * 2) + koff);
            cp_async16(smem_u32(bufB[s]) + lsw[i], Bgbase + (size_t)lrow[i] * (DIN * 2) + koff);
        }
        CP_COMMIT();
    }

    const int wid = tid >> 5;
    const int lane = tid & 31;
    const int wm = (wid & 1) * 64;
    const int wn = (wid >> 1) * 32;

    const int aRowL = (lane & 7) + ((lane >> 3) & 1) * 8;
    const int aColB = (lane >> 4) * 16;
    const int bRowL = (lane & 7) + (lane >> 4) * 8;
    const int bColB = ((lane >> 3) & 1) * 16;

    float acc[4][4][4];
#pragma unroll
    for (int mf = 0; mf < 4; mf++)
#pragma unroll
        for (int nf = 0; nf < 4; nf++)
#pragma unroll
            for (int r = 0; r < 4; r++) acc[mf][nf][r] = 0.0f;

    int stage = 0;
    int pstage = 2;
    for (int ks = 0; ks < KSTEPS; ks++) {
        if (ks + 2 < KSTEPS) { CP_WAIT(1); } else { CP_WAIT(0); }
        __syncthreads();

        if (ks + 2 < KSTEPS) {
            const size_t koff = (size_t)(ks + 2) * 128;
#pragma unroll
            for (int i = 0; i < 4; i++) {
                cp_async16(smem_u32(bufA[pstage]) + lsw[i], Agbase + (size_t)lrow[i] * (DIN * 2) + koff);
                cp_async16(smem_u32(bufB[pstage]) + lsw[i], Bgbase + (size_t)lrow[i] * (DIN * 2) + koff);
            }
            CP_COMMIT();
        }

        const unsigned sAb = smem_u32(bufA[stage]);
        const unsigned sBb = smem_u32(bufB[stage]);
#pragma unroll
        for (int k = 0; k < 4; k++) {
            const int kb = k * 32;
            unsigned a[4][4];
#pragma unroll
            for (int mf = 0; mf < 4; mf++) {
                const unsigned off = (unsigned)((wm + mf * 16 + aRowL) * 128 + kb + aColB);
                ldm_x4(sAb + SWZ(off), a[mf][0], a[mf][1], a[mf][2], a[mf][3]);
            }
            unsigned bb[8];
#pragma unroll
            for (int np = 0; np < 2; np++) {
                const unsigned off = (unsigned)((wn + np * 16 + bRowL) * 128 + kb + bColB);
                ldm_x4(sBb + SWZ(off), bb[np * 4 + 0], bb[np * 4 + 1],
                       bb[np * 4 + 2], bb[np * 4 + 3]);
            }
#pragma unroll
            for (int mf = 0; mf < 4; mf++)
#pragma unroll
                for (int nf = 0; nf < 4; nf++) {
                    const int np = nf >> 1, sub = nf & 1;
                    mma_bf16(acc[mf][nf], a[mf][0], a[mf][1], a[mf][2], a[mf][3],
                             bb[np * 4 + sub * 2], bb[np * 4 + sub * 2 + 1]);
                }
        }

        stage = (stage == 2) ? 0 : stage + 1;
        pstage = (pstage == 2) ? 0 : pstage + 1;
    }

    // Epilogue: bias + rope + bf16 store.
    const int q = lane >> 2;
    const int nlo = (lane & 3) * 2;

#pragma unroll
    for (int nf = 0; nf < 4; nf++) {
        const int n = n0 + wn + nf * 8 + nlo;
        const int which = n >> 9;
        const int nc = n & 511;
        const int o = nc >> 6;
        const int h = n & 63;
        const int f0 = h & 31;
        const float* bp = which ? be : bs;
        const float b0 = bp[nc], b1 = bp[nc + 1];
        const float scale = which ? 1.0f : 0.125f;
        __nv_bfloat16* dstb = which ? g_ER : g_SR;
#pragma unroll
        for (int mf = 0; mf < 4; mf++)
#pragma unroll
            for (int half = 0; half < 2; half++) {
                const int m = m0 + wm + mf * 16 + q + half * 8;
                const int bidx = m >> 11;
                const int spos = m & 2047;
                const float4 sc = *(const float4*)&g_tab[spos * 32 + f0];
                const float v0 = acc[mf][nf][half * 2 + 0] + b0;
                const float v1 = acc[mf][nf][half * 2 + 1] + b1;
                const float r0 = (v0 * sc.y - v1 * sc.x) * scale;
                const float r1 = (v1 * sc.w + v0 * sc.z) * scale;
                __nv_bfloat162 p;
                p.x = __float2bfloat16(r0);
                p.y = __float2bfloat16(r1);
                *(unsigned*)&dstb[(((size_t)(bidx * NHEAD + o)) * SEQ + spos) * HDIM + h]
                    = *(unsigned*)&p;
            }
    }
}

// ---------------------------------------------------------------------------
// Kernel 2: per (b,o): logits[m][n] = SR[m,:] . ER[n,:]  (K=64), bf16 HMMA.
// Fast path writes below-diagonal tiles as a pure store stream.
// ---------------------------------------------------------------------------
__global__ __launch_bounds__(256) void logits_kernel(
    const float* __restrict__ mask, float* __restrict__ out)
{
    const int z = blockIdx.z;
    const int b = z >> 3;
    const int m0 = blockIdx.y * 128;
    const int n0 = blockIdx.x * 128;
    const int tid = threadIdx.x;

    if (n0 + 127 < m0) {
        const int cb4 = (tid & 31) * 4;
        const float4 pv = *(const float4*)&mask[b * SEQ + n0 + cb4];
        float4 v;
        v.x = -(1.0f - pv.x) * NEGV - NEGV;
        v.y = -(1.0f - pv.y) * NEGV - NEGV;
        v.z = -(1.0f - pv.z) * NEGV - NEGV;
        v.w = -(1.0f - pv.w) * NEGV - NEGV;
        const int r0 = tid >> 5;
        float* base = out + ((size_t)z * SEQ + m0) * SEQ + n0 + cb4;
#pragma unroll
        for (int i = 0; i < 16; i++) {
            const int r = r0 + i * 8;
            *(float4*)(base + (size_t)r * SEQ) = v;
        }
        return;
    }

    const char* __restrict__ Ag = (const char*)(g_SR + (size_t)z * SEQ * HDIM);
    const char* __restrict__ Bg = (const char*)(g_ER + (size_t)z * SEQ * HDIM);

    __shared__ __align__(1024) char sA[128 * 128];
    __shared__ __align__(1024) char sB[128 * 128];

#pragma unroll
    for (int i = 0; i < 4; i++) {
        const int c = tid + i * 256;
        const int row = c >> 3;
        const int cb = (c & 7) * 16;
        const unsigned sw = SWZ((unsigned)(row * 128 + cb));
        *(uint4*)(sA + sw) = *(const uint4*)(Ag + (size_t)(m0 + row) * 128 + cb);
        *(uint4*)(sB + sw) = *(const uint4*)(Bg + (size_t)(n0 + row) * 128 + cb);
    }
    __syncthreads();

    const int wid = tid >> 5;
    const int lane = tid & 31;
    const int wm = (wid & 1) * 64;
    const int wn = (wid >> 1) * 32;

    const unsigned sAb = smem_u32(sA);
    const unsigned sBb = smem_u32(sB);

    float acc[4][4][4];
#pragma unroll
    for (int mf = 0; mf < 4; mf++)
#pragma unroll
        for (int nf = 0; nf < 4; nf++)
#pragma unroll
            for (int r = 0; r < 4; r++) acc[mf][nf][r] = 0.0f;

    const int aRowL = (lane & 7) + ((lane >> 3) & 1) * 8;
    const int aColB = (lane >> 4) * 16;
    const int bRowL = (lane & 7) + (lane >> 4) * 8;
    const int bColB = ((lane >> 3) & 1) * 16;

#pragma unroll
    for (int k = 0; k < 4; k++) {
        const int kb = k * 32;
        unsigned a[4][4];
#pragma unroll
        for (int mf = 0; mf < 4; mf++) {
            const unsigned off = (unsigned)((wm + mf * 16 + aRowL) * 128 + kb + aColB);
            ldm_x4(sAb + SWZ(off), a[mf][0], a[mf][1], a[mf][2], a[mf][3]);
        }
        unsigned bb[8];
#pragma unroll
        for (int np = 0; np < 2; np++) {
            const unsigned off = (unsigned)((wn + np * 16 + bRowL) * 128 + kb + bColB);
            ldm_x4(sBb + SWZ(off), bb[np * 4 + 0], bb[np * 4 + 1],
                   bb[np * 4 + 2], bb[np * 4 + 3]);
        }
#pragma unroll
        for (int mf = 0; mf < 4; mf++) {
#pragma unroll
            for (int nf = 0; nf < 4; nf++) {
                const int np = nf >> 1;
                const int sub = nf & 1;
                mma_bf16(acc[mf][nf], a[mf][0], a[mf][1], a[mf][2], a[mf][3],
                         bb[np * 4 + sub * 2], bb[np * 4 + sub * 2 + 1]);
            }
        }
    }

    const int q = lane >> 2;
    const int nlo = (lane & 3) * 2;

    float2 pv[4];
#pragma unroll
    for (int nf = 0; nf < 4; nf++) {
        const int n = n0 + wn + nf * 8 + nlo;
        pv[nf] = *(const float2*)&mask[b * SEQ + n];
    }

#pragma unroll
    for (int mf = 0; mf < 4; mf++) {
#pragma unroll
        for (int half = 0; half < 2; half++) {
            const int m = m0 + wm + mf * 16 + q + half * 8;
            float* rowp = out + ((size_t)z * SEQ + m) * SEQ;
#pragma unroll
            for (int nf = 0; nf < 4; nf++) {
                const int n = n0 + wn + nf * 8 + nlo;
                float x0 = acc[mf][nf][half * 2 + 0];
                float x1 = acc[mf][nf][half * 2 + 1];
                const float p0 = pv[nf].x, p1 = pv[nf].y;
                x0 = x0 * p0 - (1.0f - p0) * NEGV;
                x1 = x1 * p1 - (1.0f - p1) * NEGV;
                if (n < m)     x0 -= NEGV;
                if (n + 1 < m) x1 -= NEGV;
                *(float2*)(rowp + n) = make_float2(x0, x1);
            }
        }
    }
}

extern "C" void kernel_launch(void* const* d_in, const int* in_sizes, int n_in,
                              void* d_out, int out_size)
{
    const float* X    = (const float*)d_in[0];
    const float* mask = (const float*)d_in[1];
    const float* Ws   = (const float*)d_in[2];
    const float* bs   = (const float*)d_in[3];
    const float* We   = (const float*)d_in[4];
    const float* be   = (const float*)d_in[5];
    float* out = (float*)d_out;

    cudaFuncSetAttribute(proj_mma_kernel,
                         cudaFuncAttributeMaxDynamicSharedMemorySize, 98304);

    prep_kernel<<<1792, 256>>>(X, Ws, We);

    dim3 g1(NPROJ / 128, BATCH * SEQ / 128);             // (8, 32)
    proj_mma_kernel<<<g1, 256, 98304>>>(bs, be);

    dim3 g2(SEQ / 128, SEQ / 128, BATCH * NHEAD);        // (16, 16, 16)
    logits_kernel<<<g2, 256>>>(mask, out);
}